// round 10
// baseline (speedup 1.0000x reference)
#include <cuda_runtime.h>
#include <cuda_fp16.h>
#include <cstdint>

// ExpertScatter: out[b, Ind[b,h,k], :] += Y[b,h,k,:] @ W[h]
// R10: fp16 mma, TM=64 (2048 CTAs -> 6.9 waves, tail ~1%), 256-thr CTAs,
//      2 CTAs/SM, cp.async B staging from fp16 W scratch, memset zeroing.

#define BB 8
#define HH 16
#define KDIM 1024
#define DD 128
#define NN 1024
#define TT 4096

#define TM 64
#define TN 128
#define NCHUNK 8
#define THREADS 256

#define AS_BYTES (TM * DD * 2)                 // 16384
#define BS_BYTES (DD * TN * 2)                 // 32768
#define SMEM_BYTES (AS_BYTES + 2 * BS_BYTES)   // 81920 (2 CTAs = 160KB <= 227KB)

__device__ __align__(16) __half g_Wh[HH * DD * NN];   // 4 MB fp16 W scratch

__device__ __forceinline__ uint32_t pack_h2(float a, float b) {
    __half2 h = __floats2half2_rn(a, b);
    return *(uint32_t*)&h;
}

__global__ void convert_w_kernel(const float* __restrict__ src, __half* __restrict__ dst, int n8) {
    int i = blockIdx.x * blockDim.x + threadIdx.x;
    if (i >= n8) return;
    const float4 v0 = ((const float4*)src)[2 * i];
    const float4 v1 = ((const float4*)src)[2 * i + 1];
    uint4 w = { pack_h2(v0.x, v0.y), pack_h2(v0.z, v0.w),
                pack_h2(v1.x, v1.y), pack_h2(v1.z, v1.w) };
    ((uint4*)dst)[i] = w;
}

__device__ __forceinline__ uint32_t smem_u32(const void* p) {
    uint32_t a;
    asm("{ .reg .u64 t; cvta.to.shared.u64 t, %1; cvt.u32.u64 %0, t; }" : "=r"(a) : "l"(p));
    return a;
}
__device__ __forceinline__ void cp16(uint32_t dst, const void* src) {
    asm volatile("cp.async.cg.shared.global [%0], [%1], 16;" :: "r"(dst), "l"(src));
}
#define CP_COMMIT() asm volatile("cp.async.commit_group;" ::: "memory")
#define CP_WAIT0()  asm volatile("cp.async.wait_group 0;" ::: "memory")

__device__ __forceinline__ void ldsm_x4(uint32_t* r, uint32_t addr) {
    asm volatile("ldmatrix.sync.aligned.m8n8.x4.shared.b16 {%0,%1,%2,%3}, [%4];"
                 : "=r"(r[0]), "=r"(r[1]), "=r"(r[2]), "=r"(r[3]) : "r"(addr));
}
__device__ __forceinline__ void ldsm_x4_t(uint32_t* r, uint32_t addr) {
    asm volatile("ldmatrix.sync.aligned.m8n8.x4.trans.shared.b16 {%0,%1,%2,%3}, [%4];"
                 : "=r"(r[0]), "=r"(r[1]), "=r"(r[2]), "=r"(r[3]) : "r"(addr));
}
__device__ __forceinline__ void mma_f16(float* c, const uint32_t* a, const uint32_t* b) {
    asm volatile(
        "mma.sync.aligned.m16n8k16.row.col.f32.f16.f16.f32 "
        "{%0,%1,%2,%3}, {%4,%5,%6,%7}, {%8,%9}, {%0,%1,%2,%3};"
        : "+f"(c[0]), "+f"(c[1]), "+f"(c[2]), "+f"(c[3])
        : "r"(a[0]), "r"(a[1]), "r"(a[2]), "r"(a[3]), "r"(b[0]), "r"(b[1]));
}
__device__ __forceinline__ void red_v2(float* p, float x, float y) {
    asm volatile("red.global.add.v2.f32 [%0], {%1, %2};"
                 :: "l"(p), "f"(x), "f"(y) : "memory");
}

__global__ void __launch_bounds__(THREADS, 2)
expert_scatter_f16(const float* __restrict__ Y,
                   const int*   __restrict__ Ind,
                   float*       __restrict__ out) {
    // flat tile id -> (kx, h, b): 16 k-tiles per head
    const int tile = blockIdx.x;
    const int kx = tile & 15;
    const int h  = (tile >> 4) & 15;
    const int b  = tile >> 8;
    const int k0 = kx * TM;

    extern __shared__ char sm[];
    const uint32_t As_a = smem_u32(sm);
    const uint32_t Bs_a[2] = { As_a + AS_BYTES, As_a + AS_BYTES + BS_BYTES };
    __shared__ int sInd[TM];

    const int tid  = threadIdx.x;
    const int warp = tid >> 5;
    const int lane = tid & 31;
    const int g    = lane >> 2;
    const int tig  = lane & 3;
    const int wm   = warp >> 2;   // 0..1 : 32-row band
    const int wn   = warp & 3;    // 0..3 : 32-col band

    const __half* Wsrc = g_Wh + (size_t)h * DD * NN;

    // ---- Issue cp.async for B chunk 0 first ----
    #pragma unroll
    for (int i = 0; i < 8; i++) {
        const int flat = i * THREADS + tid;
        const int k = flat >> 4;
        const int c = flat & 15;
        cp16(Bs_a[0] + k * 256 + ((c ^ (k & 7)) << 4), Wsrc + (size_t)k * NN + c * 8);
    }
    CP_COMMIT();

    // ---- Stage A: Y[64m x 128k] f32 -> fp16 [m][k], c ^= m&7 ----
    const float* Yp = Y + ((size_t)(b * HH + h) * KDIM + k0) * DD;
    #pragma unroll
    for (int i = 0; i < 4; i++) {
        const int flat = i * THREADS + tid;
        const int m = flat >> 4;
        const int c = flat & 15;
        const float4 v0 = *(const float4*)(Yp + (size_t)m * DD + c * 8);
        const float4 v1 = *(const float4*)(Yp + (size_t)m * DD + c * 8 + 4);
        uint4 w = { pack_h2(v0.x, v0.y), pack_h2(v0.z, v0.w),
                    pack_h2(v1.x, v1.y), pack_h2(v1.z, v1.w) };
        asm volatile("st.shared.v4.b32 [%0], {%1,%2,%3,%4};"
                     :: "r"(As_a + m * 256 + ((c ^ (m & 7)) << 4)),
                        "r"(w.x), "r"(w.y), "r"(w.z), "r"(w.w) : "memory");
    }
    if (tid < TM) sInd[tid] = Ind[(size_t)(b * HH + h) * KDIM + k0 + tid];

    CP_WAIT0();
    __syncthreads();

    float* outb = out + (size_t)b * TT * NN;

    // per-warp scatter rows (warp tile 32m x 32n -> 2 row groups of 16)
    int t0s[2], t1s[2];
    #pragma unroll
    for (int im = 0; im < 2; im++) {
        const int mrow = wm * 32 + im * 16;
        t0s[im] = sInd[mrow + g];
        t1s[im] = sInd[mrow + g + 8];
    }

    const int a_ml_base = wm * 32 + ((lane >> 3) & 1) * 8 + (lane & 7);
    const int a_chi     = lane >> 4;
    const int b_kl_base = ((lane >> 3) & 1) * 8 + (lane & 7);

    #pragma unroll 1
    for (int nc = 0; nc < NCHUNK; nc++) {
        const int buf = nc & 1;
        const bool has_next = (nc + 1 < NCHUNK);

        // ---- Issue cp.async for next B chunk ----
        if (has_next) {
            const __half* Wn = Wsrc + (size_t)(nc + 1) * TN;
            #pragma unroll
            for (int i = 0; i < 8; i++) {
                const int flat = i * THREADS + tid;
                const int k = flat >> 4;
                const int c = flat & 15;
                cp16(Bs_a[buf ^ 1] + k * 256 + ((c ^ (k & 7)) << 4),
                     Wn + (size_t)k * NN + c * 8);
            }
            CP_COMMIT();
        }

        // ---- Compute: warp tile 32m x 32n = 2(im) x 4(in) x 8(kt) ----
        float acc[2][4][4];
        #pragma unroll
        for (int im = 0; im < 2; im++)
            #pragma unroll
            for (int in = 0; in < 4; in++)
                #pragma unroll
                for (int c = 0; c < 4; c++) acc[im][in][c] = 0.f;

        #pragma unroll
        for (int kt = 0; kt < 8; kt++) {
            uint32_t a[2][4], bfr[2][4];
            #pragma unroll
            for (int im = 0; im < 2; im++) {
                const int ml = a_ml_base + im * 16;
                const int c  = kt * 2 + a_chi;
                ldsm_x4(a[im], As_a + ml * 256 + ((c ^ (ml & 7)) << 4));
            }
            #pragma unroll
            for (int inp = 0; inp < 2; inp++) {
                const int kl = kt * 16 + b_kl_base;
                const int c  = wn * 4 + inp * 2 + (lane >> 4);
                ldsm_x4_t(bfr[inp], Bs_a[buf] + kl * 256 + ((c ^ (kl & 7)) << 4));
            }
            #pragma unroll
            for (int in = 0; in < 4; in++) {
                const uint32_t bb[2] = { bfr[in >> 1][(in & 1) * 2],
                                         bfr[in >> 1][(in & 1) * 2 + 1] };
                #pragma unroll
                for (int im = 0; im < 2; im++)
                    mma_f16(acc[im][in], a[im], bb);
            }
        }

        // ---- Epilogue: vectorized scatter-add ----
        const int colb = nc * TN + wn * 32 + tig * 2;
        #pragma unroll
        for (int im = 0; im < 2; im++) {
            float* r0 = outb + (size_t)t0s[im] * NN + colb;
            float* r1 = outb + (size_t)t1s[im] * NN + colb;
            #pragma unroll
            for (int in = 0; in < 4; in++) {
                red_v2(r0 + in * 8, acc[im][in][0], acc[im][in][1]);
                red_v2(r1 + in * 8, acc[im][in][2], acc[im][in][3]);
            }
        }

        if (has_next) {
            CP_WAIT0();
            __syncthreads();
        }
    }
}

extern "C" void kernel_launch(void* const* d_in, const int* in_sizes, int n_in,
                              void* d_out, int out_size) {
    const float* Y   = (const float*)d_in[0];
    const int*   Ind = (const int*)d_in[1];
    const float* W   = (const float*)d_in[n_in - 1];
    float* out = (float*)d_out;

    void* wh_p = nullptr;
    cudaGetSymbolAddress(&wh_p, g_Wh);

    // zero the poisoned output via memset node (graph-capturable)
    cudaMemsetAsync(out, 0, (size_t)BB * TT * NN * sizeof(float), 0);

    const int nw8 = (HH * DD * NN) / 8;
    convert_w_kernel<<<(nw8 + 511) / 512, 512>>>(W, (__half*)wh_p, nw8);

    cudaFuncSetAttribute(expert_scatter_f16,
                         cudaFuncAttributeMaxDynamicSharedMemorySize, SMEM_BYTES);
    // flat grid: 16 k-tiles x 16 heads x 8 batches = 2048 CTAs
    expert_scatter_f16<<<2048, THREADS, SMEM_BYTES>>>(Y, Ind, out);
}